// round 15
// baseline (speedup 1.0000x reference)
#include <cuda_runtime.h>
#include <math_constants.h>
#include <cstdint>

typedef unsigned long long ull;
typedef unsigned int uint;

#define NPTS 65536
#define KK   64
#define CH   64          // chunks over N for kernel A
#define LPB  (NPTS/CH)   // 1024 points per block in kernel A
#define BB   8
#define LOG2E 1.4426950408889634f
#define PI_CONST ((1.0f + 1e-8f) / 65536.0f)
#define INV_DENOM (1.0f / (1.0f + 2e-8f))

// Scratch (device globals: no allocation allowed; zero-initialized)
__device__ float  g_part[16][CH][KK][4];  // [bt][chunk][k][{S, Sx, Sy, Sz}]
__device__ float4 g_mu4[16][KK];          // [bt][k]
__device__ float  g_RT[BB][12];           // 9 R (row major) + 3 T
__device__ int    g_cnt_bt[16];
__device__ int    g_cnt_b[BB];

__device__ __forceinline__ float ex2f(float x) {
    float r; asm("ex2.approx.f32 %0, %1;" : "=f"(r) : "f"(x)); return r;
}
__device__ __forceinline__ float lg2f(float x) {
    float r; asm("lg2.approx.f32 %0, %1;" : "=f"(r) : "f"(x)); return r;
}

// ---- packed f32x2 ops (Blackwell FFMA2) ----
__device__ __forceinline__ ull fma2(ull a, ull b, ull c) {
    ull d; asm("fma.rn.f32x2 %0, %1, %2, %3;" : "=l"(d) : "l"(a), "l"(b), "l"(c)); return d;
}
__device__ __forceinline__ ull mul2(ull a, ull b) {
    ull d; asm("mul.rn.f32x2 %0, %1, %2;" : "=l"(d) : "l"(a), "l"(b)); return d;
}
__device__ __forceinline__ ull add2(ull a, ull b) {
    ull d; asm("add.rn.f32x2 %0, %1, %2;" : "=l"(d) : "l"(a), "l"(b)); return d;
}

union U2 { ull u; float2 f; };
__device__ __forceinline__ ull pack2c(float lo, float hi) {
    U2 t; t.f.x = lo; t.f.y = hi; return t.u;
}
union F4u { float4 f; ull u[2]; };

// ---------------------------------------------------------------------------
__device__ void polar3(const float* Win, float* Q)
{
    float X[9];
    #pragma unroll
    for (int i = 0; i < 9; i++) X[i] = Win[i];
    #pragma unroll 1
    for (int it = 0; it < 12; it++) {
        float c00 = X[4]*X[8] - X[5]*X[7];
        float c01 = X[5]*X[6] - X[3]*X[8];
        float c02 = X[3]*X[7] - X[4]*X[6];
        float c10 = X[2]*X[7] - X[1]*X[8];
        float c11 = X[0]*X[8] - X[2]*X[6];
        float c12 = X[1]*X[6] - X[0]*X[7];
        float c20 = X[1]*X[5] - X[2]*X[4];
        float c21 = X[2]*X[3] - X[0]*X[5];
        float c22 = X[0]*X[4] - X[1]*X[3];
        float det = X[0]*c00 + X[1]*c01 + X[2]*c02;
        float g  = ex2f(-0.3333333333f * lg2f(fabsf(det)));
        float h  = 0.5f * g;
        float h2 = __fdividef(0.5f, g * det);
        X[0] = h*X[0] + h2*c00; X[1] = h*X[1] + h2*c01; X[2] = h*X[2] + h2*c02;
        X[3] = h*X[3] + h2*c10; X[4] = h*X[4] + h2*c11; X[5] = h*X[5] + h2*c12;
        X[6] = h*X[6] + h2*c20; X[7] = h*X[7] + h2*c21; X[8] = h*X[8] + h2*c22;
    }
    #pragma unroll
    for (int i = 0; i < 9; i++) Q[i] = X[i];
}

// ---------------------------------------------------------------------------
// Kernel A: partials + fenced mu/RT tail (R12 champion) + PDL trigger.
// ---------------------------------------------------------------------------
__global__ void __launch_bounds__(256) kA(const float* __restrict__ tmpl,
                                          const float* __restrict__ src,
                                          const float* __restrict__ W)
{
    __shared__ float sm[4096];
    __shared__ int s_flag;
    const int bt = blockIdx.y;
    const int b  = bt & 7;
    const int t  = bt >> 3;
    const float* f = (t ? src : tmpl) + (size_t)b * 3 * NPTS;
    const int base = blockIdx.x * LPB;
    const int tid  = threadIdx.x;

    ((float4*)sm)[tid]       = ((const float4*)(f + base))[tid];
    ((float4*)sm)[256 + tid] = ((const float4*)(f + NPTS + base))[tid];
    ((float4*)sm)[512 + tid] = ((const float4*)(f + 2*NPTS + base))[tid];
    __syncthreads();

    // Allow the dependent kD grid to start launching (its preloads overlap us)
    asm volatile("griddepcontrol.launch_dependents;");

    {
        const int kl   = tid & 15;
        const int slot = tid >> 4;

        ull wx2[4], wy2[4], wz2[4];
        #pragma unroll
        for (int j = 0; j < 4; j++) {
            int k = kl + 16 * j;
            float wx = W[k]       * LOG2E;
            float wy = W[64 + k]  * LOG2E;
            float wz = W[128 + k] * LOG2E;
            wx2[j] = pack2c(wx, wx); wy2[j] = pack2c(wy, wy); wz2[j] = pack2c(wz, wz);
        }

        ull S2[4]  = {0, 0, 0, 0};
        ull AX2[4] = {0, 0, 0, 0};
        ull AY2[4] = {0, 0, 0, 0};
        ull AZ2[4] = {0, 0, 0, 0};

        const F4u* X = (const F4u*)sm + slot * 16;
        const F4u* Y = (const F4u*)(sm + LPB) + slot * 16;
        const F4u* Z = (const F4u*)(sm + 2*LPB) + slot * 16;

        #pragma unroll 4
        for (int i = 0; i < 16; i++) {
            F4u px = X[i], py = Y[i], pz = Z[i];
            #pragma unroll
            for (int j = 0; j < 4; j++) {
                U2 l01, l23, e01, e23;
                l01.u = fma2(wx2[j], px.u[0], fma2(wy2[j], py.u[0], mul2(wz2[j], pz.u[0])));
                l23.u = fma2(wx2[j], px.u[1], fma2(wy2[j], py.u[1], mul2(wz2[j], pz.u[1])));
                e01.f.x = ex2f(l01.f.x);  e01.f.y = ex2f(l01.f.y);
                e23.f.x = ex2f(l23.f.x);  e23.f.y = ex2f(l23.f.y);
                S2[j]  = add2(S2[j], e01.u);            S2[j]  = add2(S2[j], e23.u);
                AX2[j] = fma2(e01.u, px.u[0], AX2[j]);  AX2[j] = fma2(e23.u, px.u[1], AX2[j]);
                AY2[j] = fma2(e01.u, py.u[0], AY2[j]);  AY2[j] = fma2(e23.u, py.u[1], AY2[j]);
                AZ2[j] = fma2(e01.u, pz.u[0], AZ2[j]);  AZ2[j] = fma2(e23.u, pz.u[1], AZ2[j]);
            }
        }

        __syncthreads();
        #pragma unroll
        for (int j = 0; j < 4; j++) {
            U2 s, x, y, z;
            s.u = S2[j]; x.u = AX2[j]; y.u = AY2[j]; z.u = AZ2[j];
            float4 v = make_float4(s.f.x + s.f.y, x.f.x + x.f.y,
                                   y.f.x + y.f.y, z.f.x + z.f.y);
            ((float4*)sm)[slot * 64 + kl + 16 * j] = v;
        }
        __syncthreads();

        if (tid < 64) {
            float4 a = ((const float4*)sm)[tid];
            #pragma unroll
            for (int s = 1; s < 16; s++) {
                float4 v = ((const float4*)sm)[s * 64 + tid];
                a.x += v.x; a.y += v.y; a.z += v.z; a.w += v.w;
            }
            *(float4*)g_part[bt][blockIdx.x][tid] = a;
        }
    }

    // ---- stage A gate ----
    __syncthreads();
    if (tid == 0) { __threadfence(); s_flag = atomicAdd(&g_cnt_bt[bt], 1); }
    __syncthreads();
    if (s_flag != CH - 1) return;

    {
        const int k    = tid & 63;
        const int lane = tid >> 6;
        float4 acc = make_float4(0.f, 0.f, 0.f, 0.f);
        #pragma unroll
        for (int j = 0; j < CH/4; j++) {
            float4 p = __ldcg((const float4*)g_part[bt][lane * (CH/4) + j][k]);
            acc.x += p.x; acc.y += p.y; acc.z += p.z; acc.w += p.w;
        }
        ((float4*)sm)[lane * 64 + k] = acc;
    }
    __syncthreads();
    if (tid < 64) {
        float4 a0 = ((const float4*)sm)[tid];
        float4 a1 = ((const float4*)sm)[64 + tid];
        float4 a2 = ((const float4*)sm)[128 + tid];
        float4 a3 = ((const float4*)sm)[192 + tid];
        float S  = ((a0.x + a1.x) + (a2.x + a3.x));
        float AX = ((a0.y + a1.y) + (a2.y + a3.y));
        float AY = ((a0.z + a1.z) + (a2.z + a3.z));
        float AZ = ((a0.w + a1.w) + (a2.w + a3.w));
        float inv = INV_DENOM / S;
        g_mu4[bt][tid] = make_float4(AX * inv, AY * inv, AZ * inv, 0.f);
    }
    __syncthreads();

    // ---- stage B gate ----
    if (tid == 0) { __threadfence(); s_flag = atomicAdd(&g_cnt_b[b], 1); }
    __syncthreads();
    if (s_flag != 1) return;

    if (tid < 32) {
        const int lane = tid;
        float4 s0v = __ldcg(&g_mu4[8 + b][lane]);
        float4 s1v = __ldcg(&g_mu4[8 + b][lane + 32]);
        float4 t0v = __ldcg(&g_mu4[b][lane]);
        float4 t1v = __ldcg(&g_mu4[b][lane + 32]);
        float ms0[3] = {s0v.x, s0v.y, s0v.z};
        float ms1[3] = {s1v.x, s1v.y, s1v.z};
        float mt0[3] = {t0v.x, t0v.y, t0v.z};
        float mt1[3] = {t1v.x, t1v.y, t1v.z};

        float ss[3], st[3];
        #pragma unroll
        for (int d = 0; d < 3; d++) { ss[d] = ms0[d] + ms1[d]; st[d] = mt0[d] + mt1[d]; }
        #pragma unroll
        for (int off = 16; off; off >>= 1)
            #pragma unroll
            for (int d = 0; d < 3; d++) {
                ss[d] += __shfl_xor_sync(0xffffffffu, ss[d], off);
                st[d] += __shfl_xor_sync(0xffffffffu, st[d], off);
            }
        float cx[3], cy[3];
        #pragma unroll
        for (int d = 0; d < 3; d++) { cx[d] = PI_CONST * ss[d]; cy[d] = PI_CONST * st[d]; }

        float Wm[9];
        #pragma unroll
        for (int d = 0; d < 3; d++)
            #pragma unroll
            for (int e = 0; e < 3; e++)
                Wm[d*3+e] = (mt0[d] - cy[d]) * (ms0[e] - cx[e])
                          + (mt1[d] - cy[d]) * (ms1[e] - cx[e]);
        #pragma unroll
        for (int off = 16; off; off >>= 1)
            #pragma unroll
            for (int i = 0; i < 9; i++)
                Wm[i] += __shfl_xor_sync(0xffffffffu, Wm[i], off);

        if (lane == 0) {
            #pragma unroll
            for (int i = 0; i < 9; i++) Wm[i] *= PI_CONST;
            float Q[9];
            polar3(Wm, Q);
            float det = Q[0]*(Q[4]*Q[8]-Q[5]*Q[7])
                      - Q[1]*(Q[3]*Q[8]-Q[5]*Q[6])
                      + Q[2]*(Q[3]*Q[7]-Q[4]*Q[6]);
            if (det < 0.f) { Q[2] = -Q[2]; Q[5] = -Q[5]; Q[8] = -Q[8]; }
            float T0 = cy[0] - (Q[0]*cx[0] + Q[1]*cx[1] + Q[2]*cx[2]);
            float T1 = cy[1] - (Q[3]*cx[0] + Q[4]*cx[1] + Q[5]*cx[2]);
            float T2 = cy[2] - (Q[6]*cx[0] + Q[7]*cx[1] + Q[8]*cx[2]);
            float* rt = g_RT[b];
            #pragma unroll
            for (int i = 0; i < 9; i++) rt[i] = Q[i];
            rt[9] = T0; rt[10] = T1; rt[11] = T2;
            g_cnt_bt[b] = 0; g_cnt_bt[b + 8] = 0; g_cnt_b[b] = 0;
        }
    }
}

// ---------------------------------------------------------------------------
// Kernel D (PDL secondary): preload src (independent of R,T), then
// griddepcontrol.wait for kA completion (memory-ordered), then transform
// and store densely via smem staging. 256 blocks x 256 thr x 2048 pts.
// Safe when launched without PDL too (wait is a no-op; stream order holds).
// ---------------------------------------------------------------------------
__global__ void __launch_bounds__(256) kD(const float* __restrict__ src,
                                          float* __restrict__ out)
{
    __shared__ float4 so[1536];         // 24 KB
    const int b    = blockIdx.x >> 5;   // 32 blocks per batch
    const int tile = blockIdx.x & 31;
    const int tid  = threadIdx.x;

    // Preloads: no dependence on kA's outputs — overlap with kA's tail.
    const float* f = src + (size_t)b * 3 * NPTS + tile * 2048;
    float4 x0 = ((const float4*)f)[tid];
    float4 x1 = ((const float4*)f)[256 + tid];
    float4 y0 = ((const float4*)(f + NPTS))[tid];
    float4 y1 = ((const float4*)(f + NPTS))[256 + tid];
    float4 z0 = ((const float4*)(f + 2*NPTS))[tid];
    float4 z1 = ((const float4*)(f + 2*NPTS))[256 + tid];

    // Wait for the primary grid (kA) to complete; its g_RT writes are visible.
    asm volatile("griddepcontrol.wait;" ::: "memory");

    const float4* rtv = (const float4*)g_RT[b];
    float4 rA = __ldcg(rtv), rB = __ldcg(rtv + 1), rC = __ldcg(rtv + 2);
    float r0 = rA.x, r1 = rA.y, r2 = rA.z, r3 = rA.w;
    float r4 = rB.x, r5 = rB.y, r6 = rB.z, r7 = rB.w;
    float r8 = rC.x, t0 = rC.y, t1 = rC.z, t2 = rC.w;

    #pragma unroll
    for (int h = 0; h < 2; h++) {
        float4 px = h ? x1 : x0, py = h ? y1 : y0, pz = h ? z1 : z0;
        float X[4] = {px.x, px.y, px.z, px.w};
        float Y[4] = {py.x, py.y, py.z, py.w};
        float Z[4] = {pz.x, pz.y, pz.z, pz.w};
        float o[12];
        #pragma unroll
        for (int j = 0; j < 4; j++) {
            o[j*3 + 0] = fmaf(r0, X[j], fmaf(r1, Y[j], fmaf(r2, Z[j], t0)));
            o[j*3 + 1] = fmaf(r3, X[j], fmaf(r4, Y[j], fmaf(r5, Z[j], t1)));
            o[j*3 + 2] = fmaf(r6, X[j], fmaf(r7, Y[j], fmaf(r8, Z[j], t2)));
        }
        so[(h * 256 + tid) * 3 + 0] = make_float4(o[0], o[1], o[2],  o[3]);
        so[(h * 256 + tid) * 3 + 1] = make_float4(o[4], o[5], o[6],  o[7]);
        so[(h * 256 + tid) * 3 + 2] = make_float4(o[8], o[9], o[10], o[11]);
    }
    __syncthreads();

    float4* ob = (float4*)(out + ((size_t)b * NPTS + tile * 2048) * 3);
    #pragma unroll
    for (int i = tid; i < 1536; i += 256) ob[i] = so[i];   // dense, coalesced
}

// ---------------------------------------------------------------------------
extern "C" void kernel_launch(void* const* d_in, const int* in_sizes, int n_in,
                              void* d_out, int out_size)
{
    const float* tmpl = (const float*)d_in[0];   // (8,3,65536)
    const float* src  = (const float*)d_in[1];   // (8,3,65536)
    const float* W    = (const float*)d_in[2];   // (3,64)
    float* out        = (float*)d_out;           // (8,65536,3)

    kA<<<dim3(CH, 16), 256>>>(tmpl, src, W);

    // PDL launch of kD; fall back to a plain launch if the attribute or
    // cudaLaunchKernelEx path is rejected (stream order still correct).
    cudaLaunchConfig_t cfg = {};
    cfg.gridDim  = dim3(256, 1, 1);
    cfg.blockDim = dim3(256, 1, 1);
    cfg.dynamicSmemBytes = 0;
    cfg.stream = 0;
    cudaLaunchAttribute attr[1];
    attr[0].id = cudaLaunchAttributeProgrammaticStreamSerialization;
    attr[0].val.programmaticStreamSerializationAllowed = 1;
    cfg.attrs = attr;
    cfg.numAttrs = 1;
    cudaError_t e = cudaLaunchKernelEx(&cfg, kD, src, out);
    if (e != cudaSuccess) {
        (void)cudaGetLastError();       // clear sticky error
        kD<<<256, 256>>>(src, out);
    }
}

// round 16
// speedup vs baseline: 1.7126x; 1.7126x over previous
#include <cuda_runtime.h>
#include <math_constants.h>
#include <cstdint>

typedef unsigned long long ull;
typedef unsigned int uint;

#define NPTS 65536
#define KK   64
#define CH   64          // chunks over N for kernel A
#define LPB  (NPTS/CH)   // 1024 points per block in kernel A
#define BB   8
#define LOG2E 1.4426950408889634f
#define PI_CONST ((1.0f + 1e-8f) / 65536.0f)
#define INV_DENOM (1.0f / (1.0f + 2e-8f))

// Scratch (device globals: no allocation allowed; zero-initialized)
__device__ float  g_part[16][CH][KK][4];  // [bt][chunk][k][{S, Sx, Sy, Sz}]
__device__ float4 g_mu4[16][KK];          // [bt][k]
__device__ float  g_RT[BB][12];           // 9 R (row major) + 3 T
__device__ int    g_cnt_bt[16];
__device__ int    g_cnt_b[BB];

__device__ __forceinline__ float ex2f(float x) {
    float r; asm("ex2.approx.f32 %0, %1;" : "=f"(r) : "f"(x)); return r;
}
__device__ __forceinline__ float lg2f(float x) {
    float r; asm("lg2.approx.f32 %0, %1;" : "=f"(r) : "f"(x)); return r;
}

// ---- packed f32x2 ops (Blackwell FFMA2) ----
__device__ __forceinline__ ull fma2(ull a, ull b, ull c) {
    ull d; asm("fma.rn.f32x2 %0, %1, %2, %3;" : "=l"(d) : "l"(a), "l"(b), "l"(c)); return d;
}
__device__ __forceinline__ ull mul2(ull a, ull b) {
    ull d; asm("mul.rn.f32x2 %0, %1, %2;" : "=l"(d) : "l"(a), "l"(b)); return d;
}
__device__ __forceinline__ ull add2(ull a, ull b) {
    ull d; asm("add.rn.f32x2 %0, %1, %2;" : "=l"(d) : "l"(a), "l"(b)); return d;
}

union U2 { ull u; float2 f; };
__device__ __forceinline__ ull pack2c(float lo, float hi) {
    U2 t; t.f.x = lo; t.f.y = hi; return t.u;
}
union F4u { float4 f; ull u[2]; };

// ---------------------------------------------------------------------------
// polar decomposition of a 3x3 (scaled Newton, fp32). 8 iterations: quadratic
// convergence from the det-scaled start; fp32-converged by ~6.
// ---------------------------------------------------------------------------
__device__ void polar3(const float* Win, float* Q)
{
    float X[9];
    #pragma unroll
    for (int i = 0; i < 9; i++) X[i] = Win[i];
    #pragma unroll 1
    for (int it = 0; it < 8; it++) {
        float c00 = X[4]*X[8] - X[5]*X[7];
        float c01 = X[5]*X[6] - X[3]*X[8];
        float c02 = X[3]*X[7] - X[4]*X[6];
        float c10 = X[2]*X[7] - X[1]*X[8];
        float c11 = X[0]*X[8] - X[2]*X[6];
        float c12 = X[1]*X[6] - X[0]*X[7];
        float c20 = X[1]*X[5] - X[2]*X[4];
        float c21 = X[2]*X[3] - X[0]*X[5];
        float c22 = X[0]*X[4] - X[1]*X[3];
        float det = X[0]*c00 + X[1]*c01 + X[2]*c02;
        float g  = ex2f(-0.3333333333f * lg2f(fabsf(det)));
        float h  = 0.5f * g;
        float h2 = __fdividef(0.5f, g * det);
        X[0] = h*X[0] + h2*c00; X[1] = h*X[1] + h2*c01; X[2] = h*X[2] + h2*c02;
        X[3] = h*X[3] + h2*c10; X[4] = h*X[4] + h2*c11; X[5] = h*X[5] + h2*c12;
        X[6] = h*X[6] + h2*c20; X[7] = h*X[7] + h2*c21; X[8] = h*X[8] + h2*c22;
    }
    #pragma unroll
    for (int i = 0; i < 9; i++) Q[i] = X[i];
}

// ---------------------------------------------------------------------------
// Kernel A (R12 champion): partials + fenced mu/RT tail.
// ---------------------------------------------------------------------------
__global__ void __launch_bounds__(256) kA(const float* __restrict__ tmpl,
                                          const float* __restrict__ src,
                                          const float* __restrict__ W)
{
    __shared__ float sm[4096];
    __shared__ int s_flag;
    const int bt = blockIdx.y;
    const int b  = bt & 7;
    const int t  = bt >> 3;
    const float* f = (t ? src : tmpl) + (size_t)b * 3 * NPTS;
    const int base = blockIdx.x * LPB;
    const int tid  = threadIdx.x;

    ((float4*)sm)[tid]       = ((const float4*)(f + base))[tid];
    ((float4*)sm)[256 + tid] = ((const float4*)(f + NPTS + base))[tid];
    ((float4*)sm)[512 + tid] = ((const float4*)(f + 2*NPTS + base))[tid];
    __syncthreads();

    {
        const int kl   = tid & 15;
        const int slot = tid >> 4;

        ull wx2[4], wy2[4], wz2[4];
        #pragma unroll
        for (int j = 0; j < 4; j++) {
            int k = kl + 16 * j;
            float wx = W[k]       * LOG2E;
            float wy = W[64 + k]  * LOG2E;
            float wz = W[128 + k] * LOG2E;
            wx2[j] = pack2c(wx, wx); wy2[j] = pack2c(wy, wy); wz2[j] = pack2c(wz, wz);
        }

        ull S2[4]  = {0, 0, 0, 0};
        ull AX2[4] = {0, 0, 0, 0};
        ull AY2[4] = {0, 0, 0, 0};
        ull AZ2[4] = {0, 0, 0, 0};

        const F4u* X = (const F4u*)sm + slot * 16;
        const F4u* Y = (const F4u*)(sm + LPB) + slot * 16;
        const F4u* Z = (const F4u*)(sm + 2*LPB) + slot * 16;

        #pragma unroll 4
        for (int i = 0; i < 16; i++) {
            F4u px = X[i], py = Y[i], pz = Z[i];
            #pragma unroll
            for (int j = 0; j < 4; j++) {
                U2 l01, l23, e01, e23;
                l01.u = fma2(wx2[j], px.u[0], fma2(wy2[j], py.u[0], mul2(wz2[j], pz.u[0])));
                l23.u = fma2(wx2[j], px.u[1], fma2(wy2[j], py.u[1], mul2(wz2[j], pz.u[1])));
                e01.f.x = ex2f(l01.f.x);  e01.f.y = ex2f(l01.f.y);
                e23.f.x = ex2f(l23.f.x);  e23.f.y = ex2f(l23.f.y);
                S2[j]  = add2(S2[j], e01.u);            S2[j]  = add2(S2[j], e23.u);
                AX2[j] = fma2(e01.u, px.u[0], AX2[j]);  AX2[j] = fma2(e23.u, px.u[1], AX2[j]);
                AY2[j] = fma2(e01.u, py.u[0], AY2[j]);  AY2[j] = fma2(e23.u, py.u[1], AY2[j]);
                AZ2[j] = fma2(e01.u, pz.u[0], AZ2[j]);  AZ2[j] = fma2(e23.u, pz.u[1], AZ2[j]);
            }
        }

        __syncthreads();
        #pragma unroll
        for (int j = 0; j < 4; j++) {
            U2 s, x, y, z;
            s.u = S2[j]; x.u = AX2[j]; y.u = AY2[j]; z.u = AZ2[j];
            float4 v = make_float4(s.f.x + s.f.y, x.f.x + x.f.y,
                                   y.f.x + y.f.y, z.f.x + z.f.y);
            ((float4*)sm)[slot * 64 + kl + 16 * j] = v;
        }
        __syncthreads();

        if (tid < 64) {
            float4 a = ((const float4*)sm)[tid];
            #pragma unroll
            for (int s = 1; s < 16; s++) {
                float4 v = ((const float4*)sm)[s * 64 + tid];
                a.x += v.x; a.y += v.y; a.z += v.z; a.w += v.w;
            }
            *(float4*)g_part[bt][blockIdx.x][tid] = a;
        }
    }

    // ---- stage A gate: last block of this bt reduces the 64 chunks -> mu ----
    __syncthreads();
    if (tid == 0) { __threadfence(); s_flag = atomicAdd(&g_cnt_bt[bt], 1); }
    __syncthreads();
    if (s_flag != CH - 1) return;

    {
        const int k    = tid & 63;
        const int lane = tid >> 6;
        // two independent accumulators -> higher MLP on the 16 __ldcg loads
        float4 accA = make_float4(0.f, 0.f, 0.f, 0.f);
        float4 accB = make_float4(0.f, 0.f, 0.f, 0.f);
        #pragma unroll
        for (int j = 0; j < CH/8; j++) {
            float4 p = __ldcg((const float4*)g_part[bt][lane * (CH/4) + 2*j][k]);
            float4 q = __ldcg((const float4*)g_part[bt][lane * (CH/4) + 2*j + 1][k]);
            accA.x += p.x; accA.y += p.y; accA.z += p.z; accA.w += p.w;
            accB.x += q.x; accB.y += q.y; accB.z += q.z; accB.w += q.w;
        }
        ((float4*)sm)[lane * 64 + k] = make_float4(accA.x + accB.x, accA.y + accB.y,
                                                   accA.z + accB.z, accA.w + accB.w);
    }
    __syncthreads();
    if (tid < 64) {
        float4 a0 = ((const float4*)sm)[tid];
        float4 a1 = ((const float4*)sm)[64 + tid];
        float4 a2 = ((const float4*)sm)[128 + tid];
        float4 a3 = ((const float4*)sm)[192 + tid];
        float S  = ((a0.x + a1.x) + (a2.x + a3.x));
        float AX = ((a0.y + a1.y) + (a2.y + a3.y));
        float AY = ((a0.z + a1.z) + (a2.z + a3.z));
        float AZ = ((a0.w + a1.w) + (a2.w + a3.w));
        float inv = INV_DENOM / S;
        g_mu4[bt][tid] = make_float4(AX * inv, AY * inv, AZ * inv, 0.f);
    }
    __syncthreads();

    // ---- stage B gate: second finisher of this batch does covariance+polar --
    if (tid == 0) { __threadfence(); s_flag = atomicAdd(&g_cnt_b[b], 1); }
    __syncthreads();
    if (s_flag != 1) return;

    if (tid < 32) {
        const int lane = tid;
        float4 s0v = __ldcg(&g_mu4[8 + b][lane]);
        float4 s1v = __ldcg(&g_mu4[8 + b][lane + 32]);
        float4 t0v = __ldcg(&g_mu4[b][lane]);
        float4 t1v = __ldcg(&g_mu4[b][lane + 32]);
        float ms0[3] = {s0v.x, s0v.y, s0v.z};
        float ms1[3] = {s1v.x, s1v.y, s1v.z};
        float mt0[3] = {t0v.x, t0v.y, t0v.z};
        float mt1[3] = {t1v.x, t1v.y, t1v.z};

        float ss[3], st[3];
        #pragma unroll
        for (int d = 0; d < 3; d++) { ss[d] = ms0[d] + ms1[d]; st[d] = mt0[d] + mt1[d]; }
        #pragma unroll
        for (int off = 16; off; off >>= 1)
            #pragma unroll
            for (int d = 0; d < 3; d++) {
                ss[d] += __shfl_xor_sync(0xffffffffu, ss[d], off);
                st[d] += __shfl_xor_sync(0xffffffffu, st[d], off);
            }
        float cx[3], cy[3];
        #pragma unroll
        for (int d = 0; d < 3; d++) { cx[d] = PI_CONST * ss[d]; cy[d] = PI_CONST * st[d]; }

        float Wm[9];
        #pragma unroll
        for (int d = 0; d < 3; d++)
            #pragma unroll
            for (int e = 0; e < 3; e++)
                Wm[d*3+e] = (mt0[d] - cy[d]) * (ms0[e] - cx[e])
                          + (mt1[d] - cy[d]) * (ms1[e] - cx[e]);
        #pragma unroll
        for (int off = 16; off; off >>= 1)
            #pragma unroll
            for (int i = 0; i < 9; i++)
                Wm[i] += __shfl_xor_sync(0xffffffffu, Wm[i], off);

        if (lane == 0) {
            #pragma unroll
            for (int i = 0; i < 9; i++) Wm[i] *= PI_CONST;
            float Q[9];
            polar3(Wm, Q);
            float det = Q[0]*(Q[4]*Q[8]-Q[5]*Q[7])
                      - Q[1]*(Q[3]*Q[8]-Q[5]*Q[6])
                      + Q[2]*(Q[3]*Q[7]-Q[4]*Q[6]);
            if (det < 0.f) { Q[2] = -Q[2]; Q[5] = -Q[5]; Q[8] = -Q[8]; }
            float T0 = cy[0] - (Q[0]*cx[0] + Q[1]*cx[1] + Q[2]*cx[2]);
            float T1 = cy[1] - (Q[3]*cx[0] + Q[4]*cx[1] + Q[5]*cx[2]);
            float T2 = cy[2] - (Q[6]*cx[0] + Q[7]*cx[1] + Q[8]*cx[2]);
            float* rt = g_RT[b];
            #pragma unroll
            for (int i = 0; i < 9; i++) rt[i] = Q[i];
            rt[9] = T0; rt[10] = T1; rt[11] = T2;
            g_cnt_bt[b] = 0; g_cnt_bt[b + 8] = 0; g_cnt_b[b] = 0;
        }
    }
}

// ---------------------------------------------------------------------------
// Kernel D (R12 champion): 1024 blocks x 128 threads x 512 pts; register
// interleave -> smem -> single sync -> dense coalesced float4 stores.
// ---------------------------------------------------------------------------
__global__ void __launch_bounds__(128) kD(const float* __restrict__ src,
                                          float* __restrict__ out)
{
    __shared__ float4 so[384];          // 6 KB
    const int b    = blockIdx.x >> 7;   // 128 blocks per batch
    const int tile = blockIdx.x & 127;
    const int tid  = threadIdx.x;
    const int q    = tile * 128 + tid;  // float4 index within batch plane

    const float* f = src + (size_t)b * 3 * NPTS;
    float4 x4 = ((const float4*)f)[q];
    float4 y4 = ((const float4*)(f + NPTS))[q];
    float4 z4 = ((const float4*)(f + 2*NPTS))[q];

    const float4* rtv = (const float4*)g_RT[b];
    float4 rA = rtv[0], rB = rtv[1], rC = rtv[2];
    float r0 = rA.x, r1 = rA.y, r2 = rA.z, r3 = rA.w;
    float r4 = rB.x, r5 = rB.y, r6 = rB.z, r7 = rB.w;
    float r8 = rC.x, t0 = rC.y, t1 = rC.z, t2 = rC.w;

    float X[4] = {x4.x, x4.y, x4.z, x4.w};
    float Y[4] = {y4.x, y4.y, y4.z, y4.w};
    float Z[4] = {z4.x, z4.y, z4.z, z4.w};
    float o[12];
    #pragma unroll
    for (int j = 0; j < 4; j++) {
        o[j*3 + 0] = fmaf(r0, X[j], fmaf(r1, Y[j], fmaf(r2, Z[j], t0)));
        o[j*3 + 1] = fmaf(r3, X[j], fmaf(r4, Y[j], fmaf(r5, Z[j], t1)));
        o[j*3 + 2] = fmaf(r6, X[j], fmaf(r7, Y[j], fmaf(r8, Z[j], t2)));
    }
    so[tid*3 + 0] = make_float4(o[0], o[1], o[2],  o[3]);
    so[tid*3 + 1] = make_float4(o[4], o[5], o[6],  o[7]);
    so[tid*3 + 2] = make_float4(o[8], o[9], o[10], o[11]);
    __syncthreads();

    float4* ob = (float4*)(out + ((size_t)b * NPTS + tile * 512) * 3);
    #pragma unroll
    for (int i = tid; i < 384; i += 128) ob[i] = so[i];   // dense, coalesced
}

// ---------------------------------------------------------------------------
extern "C" void kernel_launch(void* const* d_in, const int* in_sizes, int n_in,
                              void* d_out, int out_size)
{
    const float* tmpl = (const float*)d_in[0];   // (8,3,65536)
    const float* src  = (const float*)d_in[1];   // (8,3,65536)
    const float* W    = (const float*)d_in[2];   // (3,64)
    float* out        = (float*)d_out;           // (8,65536,3)

    kA<<<dim3(CH, 16), 256>>>(tmpl, src, W);
    kD<<<1024, 128>>>(src, out);
}